// round 13
// baseline (speedup 1.0000x reference)
#include <cuda_runtime.h>
#include <math.h>
#include <stdint.h>

// Problem constants
#define Bc    2
#define Sc    2048
#define Ec    2048
#define Hc    16
#define HDc   128
#define Mrows 4096     // B*S
#define QKV_N 6144     // 3*E
#define GK    2048     // K dim of both GEMMs

// Scratch (device globals: allocation-free per harness rules)
__device__ float g_qkv[(size_t)Mrows * QKV_N];   // ~100 MB
__device__ float g_attn[(size_t)Mrows * Ec];     // ~33 MB

// ---------------------------------------------------------------------------
// Helpers
// ---------------------------------------------------------------------------
__device__ __forceinline__ uint32_t f2tf32(float x) {
    uint32_t r;
    asm("cvt.rna.tf32.f32 %0, %1;" : "=r"(r) : "f"(x));
    return r;
}
__device__ __forceinline__ uint2 split_tf32(float x) {
    uint32_t hi = f2tf32(x);
    uint32_t lo = f2tf32(x - __uint_as_float(hi));
    return make_uint2(hi, lo);
}
__device__ __forceinline__ void mma8(float* c,
                                     uint32_t a0, uint32_t a1, uint32_t a2, uint32_t a3,
                                     uint32_t b0, uint32_t b1) {
    asm volatile(
        "mma.sync.aligned.m16n8k8.row.col.f32.tf32.tf32.f32 "
        "{%0,%1,%2,%3}, {%4,%5,%6,%7}, {%8,%9}, {%0,%1,%2,%3};"
        : "+f"(c[0]), "+f"(c[1]), "+f"(c[2]), "+f"(c[3])
        : "r"(a0), "r"(a1), "r"(a2), "r"(a3), "r"(b0), "r"(b1));
}

// ---------------------------------------------------------------------------
// HYBRID dual-pipe GEMM: C[M,N] = A[M,K] @ B[N,K]^T + bias[N]
// 512 threads, 128x128 CTA tile, BK=32.
//  - warps 0-7  : cols 0-63   via mma.sync 3xTF32 (tensor pipe), warp tile 64x16
//  - warps 8-15 : cols 64-127 via fp32 SIMT (fma pipe), 8x4 per thread
// Loader writes tf32 planes (A full, B rows 0-63) + fp32 transposed
// (A full, B rows 64-127) once per slab.
// ---------------------------------------------------------------------------
#define SPAD 36            // plane row stride in uint2
#define AF_ST 132          // Af row stride (floats), rows are k
#define BF_ST 68           // Bf row stride (floats)
// smem layout (uint2 units from base):
//   Apl 0        (128*36 = 4608 u2)
//   Bpl 4608     (64*36  = 2304 u2)
//   Af  6912     (32*132 floats = 2112 u2)
//   Bf  9024     (32*68  floats = 1088 u2)
// total 10112 u2 = 80896 bytes
#define HYB_SMEM 80896

__global__ __launch_bounds__(512)
void gemm_hybrid(const float* __restrict__ A,
                 const float* __restrict__ Bw,
                 const float* __restrict__ bias,
                 float* __restrict__ C,
                 int Ndim)
{
    extern __shared__ uint2 smh[];
    uint2* Apl = smh;
    uint2* Bpl = smh + 4608;
    float* Af  = (float*)(smh + 6912);
    float* Bf  = (float*)(smh + 9024);

    const int tid  = threadIdx.x;
    const int lane = tid & 31;
    const int wid  = tid >> 5;          // 0..15
    const int bm   = blockIdx.y << 7;
    const int bn   = blockIdx.x << 7;

    // loader mapping: row = tid>>2 (0..127), 8 consecutive k's at c8
    const int lrow = tid >> 2;
    const int c8   = (tid & 3) << 3;    // 0,8,16,24
    const float* Arow = A  + (size_t)(bm + lrow) * GK + c8;
    const float* Brow = Bw + (size_t)(bn + lrow) * GK + c8;

    // ---- tensor-group state (warps 0-7) ----
    const int m_off = (wid & 1) << 6;      // 0,64
    const int n_off = (wid >> 1) << 4;     // 0,16,32,48 (for wid 0-7)
    float ct[4][2][4];
#pragma unroll
    for (int mt = 0; mt < 4; mt++)
#pragma unroll
        for (int nt = 0; nt < 2; nt++)
#pragma unroll
            for (int e = 0; e < 4; e++) ct[mt][nt][e] = 0.f;

    // ---- SIMT-group state (warps 8-15) ----
    const int st = tid - 256;              // 0..255 valid when wid>=8
    const int sy = (st >> 4) & 15;         // 0..15 -> rows 8*sy
    const int sx = st & 15;                // 0..15 -> cols 64 + 4*sx
    float cs[8][4];
#pragma unroll
    for (int i = 0; i < 8; i++)
#pragma unroll
        for (int j = 0; j < 4; j++) cs[i][j] = 0.f;

    // prefetch slab 0
    float4 pa[2], pb[2];
#pragma unroll
    for (int j = 0; j < 2; j++) {
        pa[j] = *(const float4*)(Arow + 4*j);
        pb[j] = *(const float4*)(Brow + 4*j);
    }

    const int nsteps = GK / 32;
#pragma unroll 1
    for (int step = 0; step < nsteps; step++) {
        __syncthreads();   // previous compute done with smem

        // ---- store slab: planes + fp32 transposed ----
        {
            float av[8] = {pa[0].x, pa[0].y, pa[0].z, pa[0].w,
                           pa[1].x, pa[1].y, pa[1].z, pa[1].w};
            float bv[8] = {pb[0].x, pb[0].y, pb[0].z, pb[0].w,
                           pb[1].x, pb[1].y, pb[1].z, pb[1].w};
            // A planes (all rows)
#pragma unroll
            for (int j = 0; j < 2; j++) {
                uint2 h0 = split_tf32(av[4*j+0]), h1 = split_tf32(av[4*j+1]);
                uint2 h2 = split_tf32(av[4*j+2]), h3 = split_tf32(av[4*j+3]);
                int base = lrow * SPAD + c8 + 4*j;
                *(uint4*)&Apl[base    ] = make_uint4(h0.x, h0.y, h1.x, h1.y);
                *(uint4*)&Apl[base + 2] = make_uint4(h2.x, h2.y, h3.x, h3.y);
            }
            // A fp32 transposed (all rows)
#pragma unroll
            for (int e = 0; e < 8; e++)
                Af[(c8 + e) * AF_ST + lrow] = av[e];
            // B: rows 0-63 -> planes; rows 64-127 -> fp32 transposed
            if (lrow < 64) {
#pragma unroll
                for (int j = 0; j < 2; j++) {
                    uint2 h0 = split_tf32(bv[4*j+0]), h1 = split_tf32(bv[4*j+1]);
                    uint2 h2 = split_tf32(bv[4*j+2]), h3 = split_tf32(bv[4*j+3]);
                    int base = lrow * SPAD + c8 + 4*j;
                    *(uint4*)&Bpl[base    ] = make_uint4(h0.x, h0.y, h1.x, h1.y);
                    *(uint4*)&Bpl[base + 2] = make_uint4(h2.x, h2.y, h3.x, h3.y);
                }
            } else {
#pragma unroll
                for (int e = 0; e < 8; e++)
                    Bf[(c8 + e) * BF_ST + (lrow - 64)] = bv[e];
            }
        }
        __syncthreads();

        // prefetch next slab (overlaps compute)
        if (step + 1 < nsteps) {
            int k0 = (step + 1) * 32;
#pragma unroll
            for (int j = 0; j < 2; j++) {
                pa[j] = *(const float4*)(Arow + k0 + 4*j);
                pb[j] = *(const float4*)(Brow + k0 + 4*j);
            }
        }

        if (wid < 8) {
            // ================= tensor group: mma 3xTF32 =================
#pragma unroll
            for (int kk = 0; kk < 4; kk++) {
                const int kc = (kk << 3) + (lane & 3);
                uint2 a[4][4];
#pragma unroll
                for (int mt = 0; mt < 4; mt++) {
                    int r0 = m_off + mt * 16 + (lane >> 2);
                    a[mt][0] = Apl[r0 * SPAD + kc];
                    a[mt][1] = Apl[(r0 + 8) * SPAD + kc];
                    a[mt][2] = Apl[r0 * SPAD + kc + 4];
                    a[mt][3] = Apl[(r0 + 8) * SPAD + kc + 4];
                }
                uint2 b[2][2];
#pragma unroll
                for (int nt = 0; nt < 2; nt++) {
                    int n0 = n_off + nt * 8 + (lane >> 2);
                    b[nt][0] = Bpl[n0 * SPAD + kc];
                    b[nt][1] = Bpl[n0 * SPAD + kc + 4];
                }
#pragma unroll
                for (int mt = 0; mt < 4; mt++)
#pragma unroll
                    for (int nt = 0; nt < 2; nt++) {
                        mma8(ct[mt][nt], a[mt][0].x, a[mt][1].x, a[mt][2].x, a[mt][3].x,
                                         b[nt][0].x, b[nt][1].x);
                        mma8(ct[mt][nt], a[mt][0].x, a[mt][1].x, a[mt][2].x, a[mt][3].x,
                                         b[nt][0].y, b[nt][1].y);
                        mma8(ct[mt][nt], a[mt][0].y, a[mt][1].y, a[mt][2].y, a[mt][3].y,
                                         b[nt][0].x, b[nt][1].x);
                    }
            }
        } else {
            // ================= SIMT group: fp32 FFMA =================
#pragma unroll 4
            for (int k = 0; k < 32; k++) {
                float4 a0 = *(const float4*)&Af[k * AF_ST + 8*sy];
                float4 a1 = *(const float4*)&Af[k * AF_ST + 8*sy + 4];
                float4 bq = *(const float4*)&Bf[k * BF_ST + 4*sx];
                float ar[8] = {a0.x, a0.y, a0.z, a0.w, a1.x, a1.y, a1.z, a1.w};
                float br[4] = {bq.x, bq.y, bq.z, bq.w};
#pragma unroll
                for (int i = 0; i < 8; i++)
#pragma unroll
                    for (int j = 0; j < 4; j++)
                        cs[i][j] += ar[i] * br[j];
            }
        }
    }

    // ---- epilogue ----
    if (wid < 8) {
#pragma unroll
        for (int mt = 0; mt < 4; mt++) {
            int r0 = bm + m_off + mt * 16 + (lane >> 2);
#pragma unroll
            for (int nt = 0; nt < 2; nt++) {
                int col = bn + n_off + nt * 8 + ((lane & 3) << 1);
                float b0 = bias[col], b1 = bias[col + 1];
                *(float2*)&C[(size_t)r0 * Ndim + col] =
                    make_float2(ct[mt][nt][0] + b0, ct[mt][nt][1] + b1);
                *(float2*)&C[(size_t)(r0 + 8) * Ndim + col] =
                    make_float2(ct[mt][nt][2] + b0, ct[mt][nt][3] + b1);
            }
        }
    } else {
        int colg = bn + 64 + 4*sx;
        float4 bq = *(const float4*)&bias[colg];
#pragma unroll
        for (int i = 0; i < 8; i++) {
            int r = bm + 8*sy + i;
            *(float4*)&C[(size_t)r * Ndim + colg] =
                make_float4(cs[i][0] + bq.x, cs[i][1] + bq.y,
                            cs[i][2] + bq.z, cs[i][3] + bq.w);
        }
    }
}

// ---------------------------------------------------------------------------
// Flash attention, fp32 SIMT, 512 threads (R12 passing version, unchanged)
// ---------------------------------------------------------------------------
#define SQt 128
#define SKt 64
#define DP  132

__global__ __launch_bounds__(512)
void flash_fp32_512()
{
    extern __shared__ float smf[];
    float* Qs   = smf;
    float* Ks   = Qs  + SQt*DP;
    float* Vs   = Ks  + SKt*DP;
    float* Ps   = Vs  + SKt*DP;
    float* m_s  = Ps  + SQt*SKt;
    float* l_s  = m_s + SQt;
    float* al_s = l_s + SQt;

    const int tid  = threadIdx.x;
    const int lane = tid & 31, w = tid >> 5;
    const int ty   = tid >> 4, tx  = tid & 15;
    const int b = blockIdx.z, h = blockIdx.y;
    const int q0 = blockIdx.x << 7;

    const size_t qbase = ((size_t)(b*Sc + q0)) * QKV_N + h*384;

#pragma unroll
    for (int i = 0; i < 8; i++) {
        int idx = tid + (i << 9);
        int r   = idx >> 5;
        int c4  = (idx & 31) << 2;
        *(float4*)&Qs[r*DP + c4] =
            *(const float4*)&g_qkv[qbase + (size_t)r*QKV_N + c4];
    }
    if (tid < SQt) { m_s[tid] = -INFINITY; l_s[tid] = 0.f; }

    float o[4][8];
#pragma unroll
    for (int i = 0; i < 4; i++)
#pragma unroll
        for (int c = 0; c < 8; c++) o[i][c] = 0.f;

    const float scale = 11.3137084989847604f;  // HD**0.5 (reference MULTIPLIES)

    for (int kt = 0; kt < Sc; kt += SKt) {
        __syncthreads();
        const size_t kbase = ((size_t)(b*Sc + kt)) * QKV_N + h*384;
#pragma unroll
        for (int i = 0; i < 4; i++) {
            int idx = tid + (i << 9);
            int r   = idx >> 5;
            int c4  = (idx & 31) << 2;
            *(float4*)&Ks[r*DP + c4] =
                *(const float4*)&g_qkv[kbase + (size_t)r*QKV_N + 128 + c4];
            *(float4*)&Vs[r*DP + c4] =
                *(const float4*)&g_qkv[kbase + (size_t)r*QKV_N + 256 + c4];
        }
        __syncthreads();

        float s[4][4];
#pragma unroll
        for (int i = 0; i < 4; i++)
#pragma unroll
            for (int c = 0; c < 4; c++) s[i][c] = 0.f;

#pragma unroll 8
        for (int d = 0; d < HDc; d += 4) {
            float4 kf[4];
#pragma unroll
            for (int c = 0; c < 4; c++)
                kf[c] = *(const float4*)&Ks[(tx + 16*c)*DP + d];
#pragma unroll
            for (int i = 0; i < 4; i++) {
                float4 qf = *(const float4*)&Qs[(4*ty + i)*DP + d];
#pragma unroll
                for (int c = 0; c < 4; c++)
                    s[i][c] += qf.x*kf[c].x + qf.y*kf[c].y
                             + qf.z*kf[c].z + qf.w*kf[c].w;
            }
        }
#pragma unroll
        for (int i = 0; i < 4; i++)
#pragma unroll
            for (int c = 0; c < 4; c++)
                Ps[(4*ty + i)*SKt + tx + 16*c] = s[i][c] * scale;
        __syncthreads();

#pragma unroll 1
        for (int rr = 0; rr < 8; rr++) {
            int r = (w << 3) + rr;
            float s0 = Ps[r*SKt + lane];
            float s1 = Ps[r*SKt + 32 + lane];
            float mx = fmaxf(s0, s1);
#pragma unroll
            for (int off = 16; off > 0; off >>= 1)
                mx = fmaxf(mx, __shfl_xor_sync(0xffffffffu, mx, off));
            float mo = m_s[r];
            float mn = fmaxf(mo, mx);
            float p0 = __expf(s0 - mn);
            float p1 = __expf(s1 - mn);
            float ps = p0 + p1;
#pragma unroll
            for (int off = 16; off > 0; off >>= 1)
                ps += __shfl_xor_sync(0xffffffffu, ps, off);
            Ps[r*SKt + lane]      = p0;
            Ps[r*SKt + 32 + lane] = p1;
            if (lane == 0) {
                float al = (mo == -INFINITY) ? 0.f : __expf(mo - mn);
                al_s[r] = al;
                l_s[r]  = l_s[r]*al + ps;
                m_s[r]  = mn;
            }
        }
        __syncthreads();

        float al[4];
#pragma unroll
        for (int i = 0; i < 4; i++) al[i] = al_s[4*ty + i];
#pragma unroll
        for (int i = 0; i < 4; i++)
#pragma unroll
            for (int c = 0; c < 8; c++) o[i][c] *= al[i];

#pragma unroll 4
        for (int j = 0; j < SKt; j++) {
            float p[4], v[8];
#pragma unroll
            for (int i = 0; i < 4; i++) p[i] = Ps[(4*ty + i)*SKt + j];
#pragma unroll
            for (int c = 0; c < 8; c++) v[c] = Vs[j*DP + tx + 16*c];
#pragma unroll
            for (int i = 0; i < 4; i++)
#pragma unroll
                for (int c = 0; c < 8; c++)
                    o[i][c] += p[i]*v[c];
        }
    }

#pragma unroll
    for (int i = 0; i < 4; i++) {
        int r = 4*ty + i;
        float inv = 1.0f / l_s[r];
        size_t obase = ((size_t)(b*Sc + q0 + r)) * Ec + h*HDc;
#pragma unroll
        for (int c = 0; c < 8; c++)
            g_attn[obase + tx + 16*c] = o[i][c] * inv;
    }
}

// ---------------------------------------------------------------------------
extern "C" void kernel_launch(void* const* d_in, const int* in_sizes, int n_in,
                              void* d_out, int out_size)
{
    const float* query = (const float*)d_in[0];
    const float* Wqkv  = (const float*)d_in[3];
    const float* bqkv  = (const float*)d_in[4];
    const float* Wproj = (const float*)d_in[5];
    const float* bproj = (const float*)d_in[6];
    float* out = (float*)d_out;

    float *qkvp = nullptr, *attnp = nullptr;
    cudaGetSymbolAddress((void**)&qkvp,  g_qkv);
    cudaGetSymbolAddress((void**)&attnp, g_attn);

    cudaFuncSetAttribute(gemm_hybrid,
                         cudaFuncAttributeMaxDynamicSharedMemorySize, HYB_SMEM);

    // 1) qkv = query @ Wqkv^T + bqkv   (hybrid dual-pipe)
    gemm_hybrid<<<dim3(QKV_N/128, Mrows/128), 512, HYB_SMEM>>>(
        query, Wqkv, bqkv, qkvp, QKV_N);

    // 2) flash attention (fp32, 512 threads) -> g_attn
    const int fl_smem = (SQt*DP + 2*SKt*DP + SQt*SKt + 3*SQt) * (int)sizeof(float);
    cudaFuncSetAttribute(flash_fp32_512,
                         cudaFuncAttributeMaxDynamicSharedMemorySize, fl_smem);
    flash_fp32_512<<<dim3(Sc/128, Hc, Bc), 512, fl_smem>>>();

    // 3) out = attn @ Wproj^T + bproj  (hybrid dual-pipe)
    gemm_hybrid<<<dim3(Ec/128, Mrows/128), 512, HYB_SMEM>>>(
        attnp, Wproj, bproj, out, Ec);
}

// round 14
// speedup vs baseline: 1.2569x; 1.2569x over previous
#include <cuda_runtime.h>
#include <math.h>
#include <stdint.h>

// Problem constants
#define Bc    2
#define Sc    2048
#define Ec    2048
#define Hc    16
#define HDc   128
#define Mrows 4096     // B*S
#define QKV_N 6144     // 3*E
#define GK    2048     // K dim of both GEMMs

// Scratch (device globals: allocation-free per harness rules)
__device__ float g_qkv[(size_t)Mrows * QKV_N];   // ~100 MB
__device__ float g_attn[(size_t)Mrows * Ec];     // ~33 MB

// ---------------------------------------------------------------------------
// Helpers
// ---------------------------------------------------------------------------
__device__ __forceinline__ uint32_t f2tf32(float x) {
    uint32_t r;
    asm("cvt.rna.tf32.f32 %0, %1;" : "=r"(r) : "f"(x));
    return r;
}
__device__ __forceinline__ uint2 split_tf32(float x) {
    uint32_t hi = f2tf32(x);
    uint32_t lo = f2tf32(x - __uint_as_float(hi));
    return make_uint2(hi, lo);
}
__device__ __forceinline__ void mma8(float* c,
                                     uint32_t a0, uint32_t a1, uint32_t a2, uint32_t a3,
                                     uint32_t b0, uint32_t b1) {
    asm volatile(
        "mma.sync.aligned.m16n8k8.row.col.f32.tf32.tf32.f32 "
        "{%0,%1,%2,%3}, {%4,%5,%6,%7}, {%8,%9}, {%0,%1,%2,%3};"
        : "+f"(c[0]), "+f"(c[1]), "+f"(c[2]), "+f"(c[3])
        : "r"(a0), "r"(a1), "r"(a2), "r"(a3), "r"(b0), "r"(b1));
}

// ---------------------------------------------------------------------------
// 3xTF32 tensor-core GEMM (exact R2 kernel — best measured, at HW ceiling)
// C[M,N] = A[M,K] @ B[N,K]^T + bias[N]
// ---------------------------------------------------------------------------
#define BKg 32
#define SPAD 36

__global__ __launch_bounds__(256)
void gemm_tf32x3(const float* __restrict__ A,
                 const float* __restrict__ Bw,
                 const float* __restrict__ bias,
                 float* __restrict__ C,
                 int Ndim)
{
    extern __shared__ uint2 sm2[];
    uint2* As = sm2;
    uint2* Bs = sm2 + 128 * SPAD;

    const int tid   = threadIdx.x;
    const int lane  = tid & 31;
    const int wid   = tid >> 5;
    const int m_off = (wid & 1) << 6;
    const int n_off = (wid >> 1) << 5;
    const int bm    = blockIdx.y << 7;
    const int bn    = blockIdx.x << 7;

    const int row_base = tid >> 3;
    const int col4     = (tid & 7) << 2;

    float c[4][4][4];
#pragma unroll
    for (int mt = 0; mt < 4; mt++)
#pragma unroll
        for (int nt = 0; nt < 4; nt++)
#pragma unroll
            for (int e = 0; e < 4; e++) c[mt][nt][e] = 0.f;

    float4 pa[4], pb[4];
#pragma unroll
    for (int i = 0; i < 4; i++) {
        int r = row_base + 32 * i;
        pa[i] = *(const float4*)&A [(size_t)(bm + r) * GK + col4];
        pb[i] = *(const float4*)&Bw[(size_t)(bn + r) * GK + col4];
    }

    const int nsteps = GK / BKg;
    for (int step = 0; step < nsteps; step++) {
        __syncthreads();
#pragma unroll
        for (int i = 0; i < 4; i++) {
            int r = row_base + 32 * i;
            float av[4] = {pa[i].x, pa[i].y, pa[i].z, pa[i].w};
            float bv[4] = {pb[i].x, pb[i].y, pb[i].z, pb[i].w};
            uint2 ah[4], bh[4];
#pragma unroll
            for (int j = 0; j < 4; j++) { ah[j] = split_tf32(av[j]); bh[j] = split_tf32(bv[j]); }
            *(uint4*)&As[r * SPAD + col4    ] = make_uint4(ah[0].x, ah[0].y, ah[1].x, ah[1].y);
            *(uint4*)&As[r * SPAD + col4 + 2] = make_uint4(ah[2].x, ah[2].y, ah[3].x, ah[3].y);
            *(uint4*)&Bs[r * SPAD + col4    ] = make_uint4(bh[0].x, bh[0].y, bh[1].x, bh[1].y);
            *(uint4*)&Bs[r * SPAD + col4 + 2] = make_uint4(bh[2].x, bh[2].y, bh[3].x, bh[3].y);
        }
        __syncthreads();

        if (step + 1 < nsteps) {
            int k0 = (step + 1) * BKg;
#pragma unroll
            for (int i = 0; i < 4; i++) {
                int r = row_base + 32 * i;
                pa[i] = *(const float4*)&A [(size_t)(bm + r) * GK + k0 + col4];
                pb[i] = *(const float4*)&Bw[(size_t)(bn + r) * GK + k0 + col4];
            }
        }

#pragma unroll
        for (int kk = 0; kk < 4; kk++) {
            const int kc = (kk << 3) + (lane & 3);
            uint2 a[4][4];
#pragma unroll
            for (int mt = 0; mt < 4; mt++) {
                int r0 = m_off + mt * 16 + (lane >> 2);
                a[mt][0] = As[r0 * SPAD + kc];
                a[mt][1] = As[(r0 + 8) * SPAD + kc];
                a[mt][2] = As[r0 * SPAD + kc + 4];
                a[mt][3] = As[(r0 + 8) * SPAD + kc + 4];
            }
            uint2 b[4][2];
#pragma unroll
            for (int nt = 0; nt < 4; nt++) {
                int n0 = n_off + nt * 8 + (lane >> 2);
                b[nt][0] = Bs[n0 * SPAD + kc];
                b[nt][1] = Bs[n0 * SPAD + kc + 4];
            }
#pragma unroll
            for (int mt = 0; mt < 4; mt++)
#pragma unroll
                for (int nt = 0; nt < 4; nt++) {
                    mma8(c[mt][nt], a[mt][0].x, a[mt][1].x, a[mt][2].x, a[mt][3].x,
                                    b[nt][0].x, b[nt][1].x);
                    mma8(c[mt][nt], a[mt][0].x, a[mt][1].x, a[mt][2].x, a[mt][3].x,
                                    b[nt][0].y, b[nt][1].y);
                    mma8(c[mt][nt], a[mt][0].y, a[mt][1].y, a[mt][2].y, a[mt][3].y,
                                    b[nt][0].x, b[nt][1].x);
                }
        }
    }

#pragma unroll
    for (int mt = 0; mt < 4; mt++) {
        int r0 = bm + m_off + mt * 16 + (lane >> 2);
#pragma unroll
        for (int nt = 0; nt < 4; nt++) {
            int col = bn + n_off + nt * 8 + ((lane & 3) << 1);
            float b0 = bias[col], b1 = bias[col + 1];
            *(float2*)&C[(size_t)r0 * Ndim + col] =
                make_float2(c[mt][nt][0] + b0, c[mt][nt][1] + b1);
            *(float2*)&C[(size_t)(r0 + 8) * Ndim + col] =
                make_float2(c[mt][nt][2] + b0, c[mt][nt][3] + b1);
        }
    }
}

// ---------------------------------------------------------------------------
// Flash attention v6: fp32 SIMT, 512 threads, IN-REGISTER online softmax.
// 128-q x 64-k tiles. m/l/alpha live in registers (redundant across the 16
// tx-lanes owning a row); row reductions are 4-step butterflies over tx.
// Ps holds only probabilities, written+read within the owning warp
// (__syncwarp, no CTA barrier). 2 __syncthreads per tile.
// ---------------------------------------------------------------------------
#define SQt 128
#define SKt 64
#define DP  132

__global__ __launch_bounds__(512)
void flash_v6()
{
    extern __shared__ float smf[];
    float* Qs = smf;                    // 128*132
    float* Ks = Qs + SQt*DP;            // 64*132
    float* Vs = Ks + SKt*DP;            // 64*132
    float* Ps = Vs + SKt*DP;            // 128*64 (probabilities)

    const int tid  = threadIdx.x;
    const int ty   = tid >> 4, tx = tid & 15;   // 32 x 16
    const int b = blockIdx.z, h = blockIdx.y;
    const int q0 = blockIdx.x << 7;

    const size_t qbase = ((size_t)(b*Sc + q0)) * QKV_N + h*384;
    const float scale = 11.3137084989847604f;  // HD**0.5 (reference MULTIPLIES)

    // Load Q tile (128 x 128), scale folded in
#pragma unroll
    for (int i = 0; i < 8; i++) {
        int idx = tid + (i << 9);
        int r   = idx >> 5;
        int c4  = (idx & 31) << 2;
        float4 v = *(const float4*)&g_qkv[qbase + (size_t)r*QKV_N + c4];
        v.x *= scale; v.y *= scale; v.z *= scale; v.w *= scale;
        *(float4*)&Qs[r*DP + c4] = v;
    }

    float m_r[4], l_r[4];
#pragma unroll
    for (int i = 0; i < 4; i++) { m_r[i] = -1e30f; l_r[i] = 0.f; }

    float o[4][8];
#pragma unroll
    for (int i = 0; i < 4; i++)
#pragma unroll
        for (int c = 0; c < 8; c++) o[i][c] = 0.f;

    for (int kt = 0; kt < Sc; kt += SKt) {
        __syncthreads();   // Ks/Vs free (prev PV done); covers Q load on iter 0
        const size_t kbase = ((size_t)(b*Sc + kt)) * QKV_N + h*384;
#pragma unroll
        for (int i = 0; i < 4; i++) {
            int idx = tid + (i << 9);
            int r   = idx >> 5;
            int c4  = (idx & 31) << 2;
            *(float4*)&Ks[r*DP + c4] =
                *(const float4*)&g_qkv[kbase + (size_t)r*QKV_N + 128 + c4];
            *(float4*)&Vs[r*DP + c4] =
                *(const float4*)&g_qkv[kbase + (size_t)r*QKV_N + 256 + c4];
        }
        __syncthreads();

        // ---- S = Q @ K^T (rows 4ty+i, cols tx+16c), Q pre-scaled ----
        float s[4][4];
#pragma unroll
        for (int i = 0; i < 4; i++)
#pragma unroll
            for (int c = 0; c < 4; c++) s[i][c] = 0.f;

#pragma unroll 8
        for (int d = 0; d < HDc; d += 4) {
            float4 kf[4];
#pragma unroll
            for (int c = 0; c < 4; c++)
                kf[c] = *(const float4*)&Ks[(tx + 16*c)*DP + d];
#pragma unroll
            for (int i = 0; i < 4; i++) {
                float4 qf = *(const float4*)&Qs[(4*ty + i)*DP + d];
#pragma unroll
                for (int c = 0; c < 4; c++)
                    s[i][c] += qf.x*kf[c].x + qf.y*kf[c].y
                             + qf.z*kf[c].z + qf.w*kf[c].w;
            }
        }

        // ---- in-register online softmax (butterfly over 16 tx lanes) ----
        float alpha[4];
#pragma unroll
        for (int i = 0; i < 4; i++) {
            float mx = fmaxf(fmaxf(s[i][0], s[i][1]), fmaxf(s[i][2], s[i][3]));
#pragma unroll
            for (int off = 8; off > 0; off >>= 1)
                mx = fmaxf(mx, __shfl_xor_sync(0xffffffffu, mx, off));
            float mn = fmaxf(m_r[i], mx);
            float p0 = __expf(s[i][0] - mn);
            float p1 = __expf(s[i][1] - mn);
            float p2 = __expf(s[i][2] - mn);
            float p3 = __expf(s[i][3] - mn);
            s[i][0] = p0; s[i][1] = p1; s[i][2] = p2; s[i][3] = p3;
            float ps = (p0 + p1) + (p2 + p3);
#pragma unroll
            for (int off = 8; off > 0; off >>= 1)
                ps += __shfl_xor_sync(0xffffffffu, ps, off);
            alpha[i] = __expf(m_r[i] - mn);   // ==0 when m_r=-1e30
            l_r[i] = l_r[i] * alpha[i] + ps;
            m_r[i] = mn;
        }

        // write probabilities (consumed by the SAME warp in PV)
#pragma unroll
        for (int i = 0; i < 4; i++)
#pragma unroll
            for (int c = 0; c < 4; c++)
                Ps[(4*ty + i)*SKt + tx + 16*c] = s[i][c];
        __syncwarp();

        // ---- O = O*alpha + P @ V (rows 4ty+i, cols tx+16c, 8 cols) ----
#pragma unroll
        for (int i = 0; i < 4; i++)
#pragma unroll
            for (int c = 0; c < 8; c++) o[i][c] *= alpha[i];

#pragma unroll 4
        for (int j = 0; j < SKt; j++) {
            float p[4], v[8];
#pragma unroll
            for (int i = 0; i < 4; i++) p[i] = Ps[(4*ty + i)*SKt + j];
#pragma unroll
            for (int c = 0; c < 8; c++) v[c] = Vs[j*DP + tx + 16*c];
#pragma unroll
            for (int i = 0; i < 4; i++)
#pragma unroll
                for (int c = 0; c < 8; c++)
                    o[i][c] += p[i]*v[c];
        }
    }

    // Epilogue: normalize and scatter to (b, s, h*HD + d) layout
#pragma unroll
    for (int i = 0; i < 4; i++) {
        int r = 4*ty + i;
        float inv = 1.0f / l_r[i];
        size_t obase = ((size_t)(b*Sc + q0 + r)) * Ec + h*HDc;
#pragma unroll
        for (int c = 0; c < 8; c++)
            g_attn[obase + tx + 16*c] = o[i][c] * inv;
    }
}

// ---------------------------------------------------------------------------
extern "C" void kernel_launch(void* const* d_in, const int* in_sizes, int n_in,
                              void* d_out, int out_size)
{
    const float* query = (const float*)d_in[0];
    const float* Wqkv  = (const float*)d_in[3];
    const float* bqkv  = (const float*)d_in[4];
    const float* Wproj = (const float*)d_in[5];
    const float* bproj = (const float*)d_in[6];
    float* out = (float*)d_out;

    float *qkvp = nullptr, *attnp = nullptr;
    cudaGetSymbolAddress((void**)&qkvp,  g_qkv);
    cudaGetSymbolAddress((void**)&attnp, g_attn);

    const int gemm_smem = 2 * 128 * SPAD * (int)sizeof(uint2);  // 73728
    cudaFuncSetAttribute(gemm_tf32x3,
                         cudaFuncAttributeMaxDynamicSharedMemorySize, gemm_smem);

    // 1) qkv = query @ Wqkv^T + bqkv
    gemm_tf32x3<<<dim3(QKV_N/128, Mrows/128), 256, gemm_smem>>>(
        query, Wqkv, bqkv, qkvp, QKV_N);

    // 2) flash attention v6 -> g_attn
    const int fl_smem = (SQt*DP + 2*SKt*DP + SQt*SKt) * (int)sizeof(float);
    cudaFuncSetAttribute(flash_v6,
                         cudaFuncAttributeMaxDynamicSharedMemorySize, fl_smem);
    flash_v6<<<dim3(Sc/128, Hc, Bc), 512, fl_smem>>>();

    // 3) out = attn @ Wproj^T + bproj
    gemm_tf32x3<<<dim3(Ec/128, Mrows/128), 256, gemm_smem>>>(
        attnp, Wproj, bproj, out, Ec);
}

// round 15
// speedup vs baseline: 1.3199x; 1.0501x over previous
#include <cuda_runtime.h>
#include <math.h>
#include <stdint.h>

// Problem constants
#define Bc    2
#define Sc    2048
#define Ec    2048
#define Hc    16
#define HDc   128
#define Mrows 4096     // B*S
#define QKV_N 6144     // 3*E
#define GK    2048     // K dim of both GEMMs

// Scratch (device globals: allocation-free per harness rules)
__device__ float g_qkv[(size_t)Mrows * QKV_N];   // ~100 MB
__device__ float g_attn[(size_t)Mrows * Ec];     // ~33 MB

// ---------------------------------------------------------------------------
// Helpers
// ---------------------------------------------------------------------------
__device__ __forceinline__ uint32_t f2tf32(float x) {
    uint32_t r;
    asm("cvt.rna.tf32.f32 %0, %1;" : "=r"(r) : "f"(x));
    return r;
}
__device__ __forceinline__ uint2 split_tf32(float x) {
    uint32_t hi = f2tf32(x);
    uint32_t lo = f2tf32(x - __uint_as_float(hi));
    return make_uint2(hi, lo);
}
__device__ __forceinline__ void mma8(float* c,
                                     uint32_t a0, uint32_t a1, uint32_t a2, uint32_t a3,
                                     uint32_t b0, uint32_t b1) {
    asm volatile(
        "mma.sync.aligned.m16n8k8.row.col.f32.tf32.tf32.f32 "
        "{%0,%1,%2,%3}, {%4,%5,%6,%7}, {%8,%9}, {%0,%1,%2,%3};"
        : "+f"(c[0]), "+f"(c[1]), "+f"(c[2]), "+f"(c[3])
        : "r"(a0), "r"(a1), "r"(a2), "r"(a3), "r"(b0), "r"(b1));
}

// ---------------------------------------------------------------------------
// 3x/2xTF32 tensor-core GEMM (R2 structure; adaptive term count).
// C[M,N] = A[M,K] @ B[N,K]^T + bias[N]
// vmode 0 (qkv): N-tiles with blockIdx.x%3==2 (v columns) use 2 terms,
//                q/k tiles use 3 terms (softmax-sensitive).
// vmode 1 (proj): all tiles 2 terms (linear path).
// ---------------------------------------------------------------------------
#define BKg 32
#define SPAD 36

__global__ __launch_bounds__(256)
void gemm_tf32x3(const float* __restrict__ A,
                 const float* __restrict__ Bw,
                 const float* __restrict__ bias,
                 float* __restrict__ C,
                 int Ndim, int vmode)
{
    extern __shared__ uint2 sm2[];
    uint2* As = sm2;
    uint2* Bs = sm2 + 128 * SPAD;

    const int tid   = threadIdx.x;
    const int lane  = tid & 31;
    const int wid   = tid >> 5;
    const int m_off = (wid & 1) << 6;
    const int n_off = (wid >> 1) << 5;
    const int bm    = blockIdx.y << 7;
    const int bn    = blockIdx.x << 7;

    // 3rd term (lo_a * hi_b) only on softmax-sensitive q/k columns
    const bool use3 = (vmode == 0) ? ((blockIdx.x % 3) != 2) : false;

    const int row_base = tid >> 3;
    const int col4     = (tid & 7) << 2;

    float c[4][4][4];
#pragma unroll
    for (int mt = 0; mt < 4; mt++)
#pragma unroll
        for (int nt = 0; nt < 4; nt++)
#pragma unroll
            for (int e = 0; e < 4; e++) c[mt][nt][e] = 0.f;

    float4 pa[4], pb[4];
#pragma unroll
    for (int i = 0; i < 4; i++) {
        int r = row_base + 32 * i;
        pa[i] = *(const float4*)&A [(size_t)(bm + r) * GK + col4];
        pb[i] = *(const float4*)&Bw[(size_t)(bn + r) * GK + col4];
    }

    const int nsteps = GK / BKg;
    for (int step = 0; step < nsteps; step++) {
        __syncthreads();
#pragma unroll
        for (int i = 0; i < 4; i++) {
            int r = row_base + 32 * i;
            float av[4] = {pa[i].x, pa[i].y, pa[i].z, pa[i].w};
            float bv[4] = {pb[i].x, pb[i].y, pb[i].z, pb[i].w};
            uint2 ah[4], bh[4];
#pragma unroll
            for (int j = 0; j < 4; j++) { ah[j] = split_tf32(av[j]); bh[j] = split_tf32(bv[j]); }
            *(uint4*)&As[r * SPAD + col4    ] = make_uint4(ah[0].x, ah[0].y, ah[1].x, ah[1].y);
            *(uint4*)&As[r * SPAD + col4 + 2] = make_uint4(ah[2].x, ah[2].y, ah[3].x, ah[3].y);
            *(uint4*)&Bs[r * SPAD + col4    ] = make_uint4(bh[0].x, bh[0].y, bh[1].x, bh[1].y);
            *(uint4*)&Bs[r * SPAD + col4 + 2] = make_uint4(bh[2].x, bh[2].y, bh[3].x, bh[3].y);
        }
        __syncthreads();

        if (step + 1 < nsteps) {
            int k0 = (step + 1) * BKg;
#pragma unroll
            for (int i = 0; i < 4; i++) {
                int r = row_base + 32 * i;
                pa[i] = *(const float4*)&A [(size_t)(bm + r) * GK + k0 + col4];
                pb[i] = *(const float4*)&Bw[(size_t)(bn + r) * GK + k0 + col4];
            }
        }

#pragma unroll
        for (int kk = 0; kk < 4; kk++) {
            const int kc = (kk << 3) + (lane & 3);
            uint2 a[4][4];
#pragma unroll
            for (int mt = 0; mt < 4; mt++) {
                int r0 = m_off + mt * 16 + (lane >> 2);
                a[mt][0] = As[r0 * SPAD + kc];
                a[mt][1] = As[(r0 + 8) * SPAD + kc];
                a[mt][2] = As[r0 * SPAD + kc + 4];
                a[mt][3] = As[(r0 + 8) * SPAD + kc + 4];
            }
            uint2 b[4][2];
#pragma unroll
            for (int nt = 0; nt < 4; nt++) {
                int n0 = n_off + nt * 8 + (lane >> 2);
                b[nt][0] = Bs[n0 * SPAD + kc];
                b[nt][1] = Bs[n0 * SPAD + kc + 4];
            }
#pragma unroll
            for (int mt = 0; mt < 4; mt++)
#pragma unroll
                for (int nt = 0; nt < 4; nt++) {
                    mma8(c[mt][nt], a[mt][0].x, a[mt][1].x, a[mt][2].x, a[mt][3].x,
                                    b[nt][0].x, b[nt][1].x);
                    mma8(c[mt][nt], a[mt][0].x, a[mt][1].x, a[mt][2].x, a[mt][3].x,
                                    b[nt][0].y, b[nt][1].y);
                }
            if (use3) {
#pragma unroll
                for (int mt = 0; mt < 4; mt++)
#pragma unroll
                    for (int nt = 0; nt < 4; nt++)
                        mma8(c[mt][nt], a[mt][0].y, a[mt][1].y, a[mt][2].y, a[mt][3].y,
                                        b[nt][0].x, b[nt][1].x);
            }
        }
    }

#pragma unroll
    for (int mt = 0; mt < 4; mt++) {
        int r0 = bm + m_off + mt * 16 + (lane >> 2);
#pragma unroll
        for (int nt = 0; nt < 4; nt++) {
            int col = bn + n_off + nt * 8 + ((lane & 3) << 1);
            float b0 = bias[col], b1 = bias[col + 1];
            *(float2*)&C[(size_t)r0 * Ndim + col] =
                make_float2(c[mt][nt][0] + b0, c[mt][nt][1] + b1);
            *(float2*)&C[(size_t)(r0 + 8) * Ndim + col] =
                make_float2(c[mt][nt][2] + b0, c[mt][nt][3] + b1);
        }
    }
}

// ---------------------------------------------------------------------------
// Flash attention v6: fp32 SIMT, 512 threads, in-register online softmax
// (R14 passing version, unchanged)
// ---------------------------------------------------------------------------
#define SQt 128
#define SKt 64
#define DP  132

__global__ __launch_bounds__(512)
void flash_v6()
{
    extern __shared__ float smf[];
    float* Qs = smf;                    // 128*132
    float* Ks = Qs + SQt*DP;            // 64*132
    float* Vs = Ks + SKt*DP;            // 64*132
    float* Ps = Vs + SKt*DP;            // 128*64 (probabilities)

    const int tid  = threadIdx.x;
    const int ty   = tid >> 4, tx = tid & 15;   // 32 x 16
    const int b = blockIdx.z, h = blockIdx.y;
    const int q0 = blockIdx.x << 7;

    const size_t qbase = ((size_t)(b*Sc + q0)) * QKV_N + h*384;
    const float scale = 11.3137084989847604f;  // HD**0.5 (reference MULTIPLIES)

#pragma unroll
    for (int i = 0; i < 8; i++) {
        int idx = tid + (i << 9);
        int r   = idx >> 5;
        int c4  = (idx & 31) << 2;
        float4 v = *(const float4*)&g_qkv[qbase + (size_t)r*QKV_N + c4];
        v.x *= scale; v.y *= scale; v.z *= scale; v.w *= scale;
        *(float4*)&Qs[r*DP + c4] = v;
    }

    float m_r[4], l_r[4];
#pragma unroll
    for (int i = 0; i < 4; i++) { m_r[i] = -1e30f; l_r[i] = 0.f; }

    float o[4][8];
#pragma unroll
    for (int i = 0; i < 4; i++)
#pragma unroll
        for (int c = 0; c < 8; c++) o[i][c] = 0.f;

    for (int kt = 0; kt < Sc; kt += SKt) {
        __syncthreads();
        const size_t kbase = ((size_t)(b*Sc + kt)) * QKV_N + h*384;
#pragma unroll
        for (int i = 0; i < 4; i++) {
            int idx = tid + (i << 9);
            int r   = idx >> 5;
            int c4  = (idx & 31) << 2;
            *(float4*)&Ks[r*DP + c4] =
                *(const float4*)&g_qkv[kbase + (size_t)r*QKV_N + 128 + c4];
            *(float4*)&Vs[r*DP + c4] =
                *(const float4*)&g_qkv[kbase + (size_t)r*QKV_N + 256 + c4];
        }
        __syncthreads();

        float s[4][4];
#pragma unroll
        for (int i = 0; i < 4; i++)
#pragma unroll
            for (int c = 0; c < 4; c++) s[i][c] = 0.f;

#pragma unroll 8
        for (int d = 0; d < HDc; d += 4) {
            float4 kf[4];
#pragma unroll
            for (int c = 0; c < 4; c++)
                kf[c] = *(const float4*)&Ks[(tx + 16*c)*DP + d];
#pragma unroll
            for (int i = 0; i < 4; i++) {
                float4 qf = *(const float4*)&Qs[(4*ty + i)*DP + d];
#pragma unroll
                for (int c = 0; c < 4; c++)
                    s[i][c] += qf.x*kf[c].x + qf.y*kf[c].y
                             + qf.z*kf[c].z + qf.w*kf[c].w;
            }
        }

        float alpha[4];
#pragma unroll
        for (int i = 0; i < 4; i++) {
            float mx = fmaxf(fmaxf(s[i][0], s[i][1]), fmaxf(s[i][2], s[i][3]));
#pragma unroll
            for (int off = 8; off > 0; off >>= 1)
                mx = fmaxf(mx, __shfl_xor_sync(0xffffffffu, mx, off));
            float mn = fmaxf(m_r[i], mx);
            float p0 = __expf(s[i][0] - mn);
            float p1 = __expf(s[i][1] - mn);
            float p2 = __expf(s[i][2] - mn);
            float p3 = __expf(s[i][3] - mn);
            s[i][0] = p0; s[i][1] = p1; s[i][2] = p2; s[i][3] = p3;
            float ps = (p0 + p1) + (p2 + p3);
#pragma unroll
            for (int off = 8; off > 0; off >>= 1)
                ps += __shfl_xor_sync(0xffffffffu, ps, off);
            alpha[i] = __expf(m_r[i] - mn);
            l_r[i] = l_r[i] * alpha[i] + ps;
            m_r[i] = mn;
        }

#pragma unroll
        for (int i = 0; i < 4; i++)
#pragma unroll
            for (int c = 0; c < 4; c++)
                Ps[(4*ty + i)*SKt + tx + 16*c] = s[i][c];
        __syncwarp();

#pragma unroll
        for (int i = 0; i < 4; i++)
#pragma unroll
            for (int c = 0; c < 8; c++) o[i][c] *= alpha[i];

#pragma unroll 4
        for (int j = 0; j < SKt; j++) {
            float p[4], v[8];
#pragma unroll
            for (int i = 0; i < 4; i++) p[i] = Ps[(4*ty + i)*SKt + j];
#pragma unroll
            for (int c = 0; c < 8; c++) v[c] = Vs[j*DP + tx + 16*c];
#pragma unroll
            for (int i = 0; i < 4; i++)
#pragma unroll
                for (int c = 0; c < 8; c++)
                    o[i][c] += p[i]*v[c];
        }
    }

#pragma unroll
    for (int i = 0; i < 4; i++) {
        int r = 4*ty + i;
        float inv = 1.0f / l_r[i];
        size_t obase = ((size_t)(b*Sc + q0 + r)) * Ec + h*HDc;
#pragma unroll
        for (int c = 0; c < 8; c++)
            g_attn[obase + tx + 16*c] = o[i][c] * inv;
    }
}

// ---------------------------------------------------------------------------
extern "C" void kernel_launch(void* const* d_in, const int* in_sizes, int n_in,
                              void* d_out, int out_size)
{
    const float* query = (const float*)d_in[0];
    const float* Wqkv  = (const float*)d_in[3];
    const float* bqkv  = (const float*)d_in[4];
    const float* Wproj = (const float*)d_in[5];
    const float* bproj = (const float*)d_in[6];
    float* out = (float*)d_out;

    float *qkvp = nullptr, *attnp = nullptr;
    cudaGetSymbolAddress((void**)&qkvp,  g_qkv);
    cudaGetSymbolAddress((void**)&attnp, g_attn);

    const int gemm_smem = 2 * 128 * SPAD * (int)sizeof(uint2);  // 73728
    cudaFuncSetAttribute(gemm_tf32x3,
                         cudaFuncAttributeMaxDynamicSharedMemorySize, gemm_smem);

    // 1) qkv = query @ Wqkv^T + bqkv  (q/k tiles 3-term, v tiles 2-term)
    gemm_tf32x3<<<dim3(QKV_N/128, Mrows/128), 256, gemm_smem>>>(
        query, Wqkv, bqkv, qkvp, QKV_N, 0);

    // 2) flash attention v6 -> g_attn
    const int fl_smem = (SQt*DP + 2*SKt*DP + SQt*SKt) * (int)sizeof(float);
    cudaFuncSetAttribute(flash_v6,
                         cudaFuncAttributeMaxDynamicSharedMemorySize, fl_smem);
    flash_v6<<<dim3(Sc/128, Hc, Bc), 512, fl_smem>>>();

    // 3) out = attn @ Wproj^T + bproj  (all tiles 2-term, linear path)
    gemm_tf32x3<<<dim3(Ec/128, Mrows/128), 256, gemm_smem>>>(
        attnp, Wproj, bproj, out, Ec, 1);
}

// round 16
// speedup vs baseline: 1.3403x; 1.0155x over previous
#include <cuda_runtime.h>
#include <math.h>
#include <stdint.h>

// Problem constants
#define Bc    2
#define Sc    2048
#define Ec    2048
#define Hc    16
#define HDc   128
#define Mrows 4096     // B*S
#define QKV_N 6144     // 3*E
#define GK    2048     // K dim of both GEMMs

// Scratch (device globals: allocation-free per harness rules)
__device__ float g_qkv[(size_t)Mrows * QKV_N];   // ~100 MB
__device__ float g_attn[(size_t)Mrows * Ec];     // ~33 MB

// ---------------------------------------------------------------------------
// Helpers
// ---------------------------------------------------------------------------
__device__ __forceinline__ uint32_t f2tf32(float x) {
    uint32_t r;
    asm("cvt.rna.tf32.f32 %0, %1;" : "=r"(r) : "f"(x));
    return r;
}
__device__ __forceinline__ void mma8(float* c,
                                     uint32_t a0, uint32_t a1, uint32_t a2, uint32_t a3,
                                     uint32_t b0, uint32_t b1) {
    asm volatile(
        "mma.sync.aligned.m16n8k8.row.col.f32.tf32.tf32.f32 "
        "{%0,%1,%2,%3}, {%4,%5,%6,%7}, {%8,%9}, {%0,%1,%2,%3};"
        : "+f"(c[0]), "+f"(c[1]), "+f"(c[2]), "+f"(c[3])
        : "r"(a0), "r"(a1), "r"(a2), "r"(a3), "r"(b0), "r"(b1));
}

// ---------------------------------------------------------------------------
// Adaptive-precision TF32 GEMM (R2 structure).
// C[M,N] = A[M,K] @ B[N,K]^T + bias[N]
// terms per CTA:
//   vmode 0 (qkv): q/k tiles (bx%3!=2) -> 3 terms; v tiles -> 1 term
//   vmode 1 (proj): all tiles 1 term (linear path, error not amplified)
// Loader computes only the lo-planes the CTA will consume.
// ---------------------------------------------------------------------------
#define BKg 32
#define SPAD 36

__global__ __launch_bounds__(256)
void gemm_tf32x3(const float* __restrict__ A,
                 const float* __restrict__ Bw,
                 const float* __restrict__ bias,
                 float* __restrict__ C,
                 int Ndim, int vmode)
{
    extern __shared__ uint2 sm2[];
    uint2* As = sm2;
    uint2* Bs = sm2 + 128 * SPAD;

    const int tid   = threadIdx.x;
    const int lane  = tid & 31;
    const int wid   = tid >> 5;
    const int m_off = (wid & 1) << 6;
    const int n_off = (wid >> 1) << 5;
    const int bm    = blockIdx.y << 7;
    const int bn    = blockIdx.x << 7;

    const int terms = (vmode == 0) ? (((blockIdx.x % 3) != 2) ? 3 : 1) : 1;
    const bool need_alo = (terms == 3);
    const bool need_blo = (terms >= 2);

    const int row_base = tid >> 3;
    const int col4     = (tid & 7) << 2;

    float c[4][4][4];
#pragma unroll
    for (int mt = 0; mt < 4; mt++)
#pragma unroll
        for (int nt = 0; nt < 4; nt++)
#pragma unroll
            for (int e = 0; e < 4; e++) c[mt][nt][e] = 0.f;

    float4 pa[4], pb[4];
#pragma unroll
    for (int i = 0; i < 4; i++) {
        int r = row_base + 32 * i;
        pa[i] = *(const float4*)&A [(size_t)(bm + r) * GK + col4];
        pb[i] = *(const float4*)&Bw[(size_t)(bn + r) * GK + col4];
    }

    const int nsteps = GK / BKg;
    for (int step = 0; step < nsteps; step++) {
        __syncthreads();
#pragma unroll
        for (int i = 0; i < 4; i++) {
            int r = row_base + 32 * i;
            float av[4] = {pa[i].x, pa[i].y, pa[i].z, pa[i].w};
            float bv[4] = {pb[i].x, pb[i].y, pb[i].z, pb[i].w};
            uint32_t ah[4], al[4], bh[4], bl[4];
#pragma unroll
            for (int j = 0; j < 4; j++) {
                ah[j] = f2tf32(av[j]);
                al[j] = need_alo ? f2tf32(av[j] - __uint_as_float(ah[j])) : 0u;
                bh[j] = f2tf32(bv[j]);
                bl[j] = need_blo ? f2tf32(bv[j] - __uint_as_float(bh[j])) : 0u;
            }
            *(uint4*)&As[r * SPAD + col4    ] = make_uint4(ah[0], al[0], ah[1], al[1]);
            *(uint4*)&As[r * SPAD + col4 + 2] = make_uint4(ah[2], al[2], ah[3], al[3]);
            *(uint4*)&Bs[r * SPAD + col4    ] = make_uint4(bh[0], bl[0], bh[1], bl[1]);
            *(uint4*)&Bs[r * SPAD + col4 + 2] = make_uint4(bh[2], bl[2], bh[3], bl[3]);
        }
        __syncthreads();

        if (step + 1 < nsteps) {
            int k0 = (step + 1) * BKg;
#pragma unroll
            for (int i = 0; i < 4; i++) {
                int r = row_base + 32 * i;
                pa[i] = *(const float4*)&A [(size_t)(bm + r) * GK + k0 + col4];
                pb[i] = *(const float4*)&Bw[(size_t)(bn + r) * GK + k0 + col4];
            }
        }

#pragma unroll
        for (int kk = 0; kk < 4; kk++) {
            const int kc = (kk << 3) + (lane & 3);
            uint2 a[4][4];
#pragma unroll
            for (int mt = 0; mt < 4; mt++) {
                int r0 = m_off + mt * 16 + (lane >> 2);
                a[mt][0] = As[r0 * SPAD + kc];
                a[mt][1] = As[(r0 + 8) * SPAD + kc];
                a[mt][2] = As[r0 * SPAD + kc + 4];
                a[mt][3] = As[(r0 + 8) * SPAD + kc + 4];
            }
            uint2 b[4][2];
#pragma unroll
            for (int nt = 0; nt < 4; nt++) {
                int n0 = n_off + nt * 8 + (lane >> 2);
                b[nt][0] = Bs[n0 * SPAD + kc];
                b[nt][1] = Bs[n0 * SPAD + kc + 4];
            }
            // term 1: hi*hi (always)
#pragma unroll
            for (int mt = 0; mt < 4; mt++)
#pragma unroll
                for (int nt = 0; nt < 4; nt++)
                    mma8(c[mt][nt], a[mt][0].x, a[mt][1].x, a[mt][2].x, a[mt][3].x,
                                    b[nt][0].x, b[nt][1].x);
            // term 2: hi*lo
            if (terms >= 2) {
#pragma unroll
                for (int mt = 0; mt < 4; mt++)
#pragma unroll
                    for (int nt = 0; nt < 4; nt++)
                        mma8(c[mt][nt], a[mt][0].x, a[mt][1].x, a[mt][2].x, a[mt][3].x,
                                        b[nt][0].y, b[nt][1].y);
            }
            // term 3: lo*hi
            if (terms == 3) {
#pragma unroll
                for (int mt = 0; mt < 4; mt++)
#pragma unroll
                    for (int nt = 0; nt < 4; nt++)
                        mma8(c[mt][nt], a[mt][0].y, a[mt][1].y, a[mt][2].y, a[mt][3].y,
                                        b[nt][0].x, b[nt][1].x);
            }
        }
    }

#pragma unroll
    for (int mt = 0; mt < 4; mt++) {
        int r0 = bm + m_off + mt * 16 + (lane >> 2);
#pragma unroll
        for (int nt = 0; nt < 4; nt++) {
            int col = bn + n_off + nt * 8 + ((lane & 3) << 1);
            float b0 = bias[col], b1 = bias[col + 1];
            *(float2*)&C[(size_t)r0 * Ndim + col] =
                make_float2(c[mt][nt][0] + b0, c[mt][nt][1] + b1);
            *(float2*)&C[(size_t)(r0 + 8) * Ndim + col] =
                make_float2(c[mt][nt][2] + b0, c[mt][nt][3] + b1);
        }
    }
}

// ---------------------------------------------------------------------------
// Flash attention v6: fp32 SIMT, 512 threads, in-register online softmax
// (R14/R15 passing version, unchanged)
// ---------------------------------------------------------------------------
#define SQt 128
#define SKt 64
#define DP  132

__global__ __launch_bounds__(512)
void flash_v6()
{
    extern __shared__ float smf[];
    float* Qs = smf;                    // 128*132
    float* Ks = Qs + SQt*DP;            // 64*132
    float* Vs = Ks + SKt*DP;            // 64*132
    float* Ps = Vs + SKt*DP;            // 128*64 (probabilities)

    const int tid  = threadIdx.x;
    const int ty   = tid >> 4, tx = tid & 15;   // 32 x 16
    const int b = blockIdx.z, h = blockIdx.y;
    const int q0 = blockIdx.x << 7;

    const size_t qbase = ((size_t)(b*Sc + q0)) * QKV_N + h*384;
    const float scale = 11.3137084989847604f;  // HD**0.5 (reference MULTIPLIES)

#pragma unroll
    for (int i = 0; i < 8; i++) {
        int idx = tid + (i << 9);
        int r   = idx >> 5;
        int c4  = (idx & 31) << 2;
        float4 v = *(const float4*)&g_qkv[qbase + (size_t)r*QKV_N + c4];
        v.x *= scale; v.y *= scale; v.z *= scale; v.w *= scale;
        *(float4*)&Qs[r*DP + c4] = v;
    }

    float m_r[4], l_r[4];
#pragma unroll
    for (int i = 0; i < 4; i++) { m_r[i] = -1e30f; l_r[i] = 0.f; }

    float o[4][8];
#pragma unroll
    for (int i = 0; i < 4; i++)
#pragma unroll
        for (int c = 0; c < 8; c++) o[i][c] = 0.f;

    for (int kt = 0; kt < Sc; kt += SKt) {
        __syncthreads();
        const size_t kbase = ((size_t)(b*Sc + kt)) * QKV_N + h*384;
#pragma unroll
        for (int i = 0; i < 4; i++) {
            int idx = tid + (i << 9);
            int r   = idx >> 5;
            int c4  = (idx & 31) << 2;
            *(float4*)&Ks[r*DP + c4] =
                *(const float4*)&g_qkv[kbase + (size_t)r*QKV_N + 128 + c4];
            *(float4*)&Vs[r*DP + c4] =
                *(const float4*)&g_qkv[kbase + (size_t)r*QKV_N + 256 + c4];
        }
        __syncthreads();

        float s[4][4];
#pragma unroll
        for (int i = 0; i < 4; i++)
#pragma unroll
            for (int c = 0; c < 4; c++) s[i][c] = 0.f;

#pragma unroll 8
        for (int d = 0; d < HDc; d += 4) {
            float4 kf[4];
#pragma unroll
            for (int c = 0; c < 4; c++)
                kf[c] = *(const float4*)&Ks[(tx + 16*c)*DP + d];
#pragma unroll
            for (int i = 0; i < 4; i++) {
                float4 qf = *(const float4*)&Qs[(4*ty + i)*DP + d];
#pragma unroll
                for (int c = 0; c < 4; c++)
                    s[i][c] += qf.x*kf[c].x + qf.y*kf[c].y
                             + qf.z*kf[c].z + qf.w*kf[c].w;
            }
        }

        float alpha[4];
#pragma unroll
        for (int i = 0; i < 4; i++) {
            float mx = fmaxf(fmaxf(s[i][0], s[i][1]), fmaxf(s[i][2], s[i][3]));
#pragma unroll
            for (int off = 8; off > 0; off >>= 1)
                mx = fmaxf(mx, __shfl_xor_sync(0xffffffffu, mx, off));
            float mn = fmaxf(m_r[i], mx);
            float p0 = __expf(s[i][0] - mn);
            float p1 = __expf(s[i][1] - mn);
            float p2 = __expf(s[i][2] - mn);
            float p3 = __expf(s[i][3] - mn);
            s[i][0] = p0; s[i][1] = p1; s[i][2] = p2; s[i][3] = p3;
            float ps = (p0 + p1) + (p2 + p3);
#pragma unroll
            for (int off = 8; off > 0; off >>= 1)
                ps += __shfl_xor_sync(0xffffffffu, ps, off);
            alpha[i] = __expf(m_r[i] - mn);
            l_r[i] = l_r[i] * alpha[i] + ps;
            m_r[i] = mn;
        }

#pragma unroll
        for (int i = 0; i < 4; i++)
#pragma unroll
            for (int c = 0; c < 4; c++)
                Ps[(4*ty + i)*SKt + tx + 16*c] = s[i][c];
        __syncwarp();

#pragma unroll
        for (int i = 0; i < 4; i++)
#pragma unroll
            for (int c = 0; c < 8; c++) o[i][c] *= alpha[i];

#pragma unroll 4
        for (int j = 0; j < SKt; j++) {
            float p[4], v[8];
#pragma unroll
            for (int i = 0; i < 4; i++) p[i] = Ps[(4*ty + i)*SKt + j];
#pragma unroll
            for (int c = 0; c < 8; c++) v[c] = Vs[j*DP + tx + 16*c];
#pragma unroll
            for (int i = 0; i < 4; i++)
#pragma unroll
                for (int c = 0; c < 8; c++)
                    o[i][c] += p[i]*v[c];
        }
    }

#pragma unroll
    for (int i = 0; i < 4; i++) {
        int r = 4*ty + i;
        float inv = 1.0f / l_r[i];
        size_t obase = ((size_t)(b*Sc + q0 + r)) * Ec + h*HDc;
#pragma unroll
        for (int c = 0; c < 8; c++)
            g_attn[obase + tx + 16*c] = o[i][c] * inv;
    }
}

// ---------------------------------------------------------------------------
extern "C" void kernel_launch(void* const* d_in, const int* in_sizes, int n_in,
                              void* d_out, int out_size)
{
    const float* query = (const float*)d_in[0];
    const float* Wqkv  = (const float*)d_in[3];
    const float* bqkv  = (const float*)d_in[4];
    const float* Wproj = (const float*)d_in[5];
    const float* bproj = (const float*)d_in[6];
    float* out = (float*)d_out;

    float *qkvp = nullptr, *attnp = nullptr;
    cudaGetSymbolAddress((void**)&qkvp,  g_qkv);
    cudaGetSymbolAddress((void**)&attnp, g_attn);

    const int gemm_smem = 2 * 128 * SPAD * (int)sizeof(uint2);  // 73728
    cudaFuncSetAttribute(gemm_tf32x3,
                         cudaFuncAttributeMaxDynamicSharedMemorySize, gemm_smem);

    // 1) qkv = query @ Wqkv^T + bqkv  (q/k tiles 3-term, v tiles 1-term)
    gemm_tf32x3<<<dim3(QKV_N/128, Mrows/128), 256, gemm_smem>>>(
        query, Wqkv, bqkv, qkvp, QKV_N, 0);

    // 2) flash attention v6 -> g_attn
    const int fl_smem = (SQt*DP + 2*SKt*DP + SQt*SKt) * (int)sizeof(float);
    cudaFuncSetAttribute(flash_v6,
                         cudaFuncAttributeMaxDynamicSharedMemorySize, fl_smem);
    flash_v6<<<dim3(Sc/128, Hc, Bc), 512, fl_smem>>>();

    // 3) out = attn @ Wproj^T + bproj  (all tiles 1-term, linear path)
    gemm_tf32x3<<<dim3(Ec/128, Mrows/128), 256, gemm_smem>>>(
        attnp, Wproj, bproj, out, Ec, 1);
}